// round 14
// baseline (speedup 1.0000x reference)
#include <cuda_runtime.h>

#define N_NODES 4096
#define D_EMB   256
#define H_HEADS 4
#define DH      64
#define E_EDGES 131072
#define MAXDEG  256
#define ALPHA   0.2f
#define BITW    (N_NODES / 32)
#define NBLK    148            // == #SMs; co-residency guaranteed
#define NWARPS  (NBLK * 8)

// ---- scratch (__device__ globals; no allocations allowed) ----
// g_bits zero-initialized at load; scansoft re-zeros after reading, so every
// launch / graph replay sees a clean bitmask.
__device__ unsigned g_bits[N_NODES * BITW];
__device__ int      g_deg [N_NODES];
__device__ int      g_nbr [N_NODES * MAXDEG];
__device__ float    g_h   [N_NODES * D_EMB];
__device__ float    g_esrc[H_HEADS * N_NODES];
__device__ float    g_edst[H_HEADS * N_NODES];
__device__ float    g_wt  [N_NODES * H_HEADS * MAXDEG];
__device__ unsigned g_arr[2], g_rel[2];          // grid barrier state

__device__ __forceinline__ float leaky(float v) { return v >= 0.f ? v : ALPHA * v; }

// ---- 3xTF32 helpers: a = hi + lo; hi*hi + hi*lo + lo*hi ~ fp32 accuracy ----
__device__ __forceinline__ void totf(float a, unsigned& hi, unsigned& lo) {
    asm("cvt.rna.tf32.f32 %0, %1;" : "=r"(hi) : "f"(a));
    float r = a - __uint_as_float(hi);
    asm("cvt.rna.tf32.f32 %0, %1;" : "=r"(lo) : "f"(r));
}
__device__ __forceinline__ void mma8(float* c, const unsigned* a, const unsigned* b) {
    asm("mma.sync.aligned.m16n8k8.row.col.f32.tf32.tf32.f32 "
        "{%0,%1,%2,%3}, {%4,%5,%6,%7}, {%8,%9}, {%0,%1,%2,%3};"
        : "+f"(c[0]), "+f"(c[1]), "+f"(c[2]), "+f"(c[3])
        : "r"(a[0]), "r"(a[1]), "r"(a[2]), "r"(a[3]), "r"(b[0]), "r"(b[1]));
}

// ---- generation-counting grid barrier (replay-safe, no counter reset) ----
__device__ __forceinline__ void gridsync(int b) {
    __syncthreads();
    if (threadIdx.x == 0) {
        __threadfence();
        unsigned nb = gridDim.x;
        unsigned v = atomicAdd(&g_arr[b], 1u) + 1u;
        unsigned gen = (v + nb - 1u) / nb;
        if (v == gen * nb) {
            atomicAdd(&g_rel[b], 1u);            // last arrival releases
        } else {
            while (atomicAdd(&g_rel[b], 0u) < gen) { }
        }
        __threadfence();
    }
    __syncthreads();
}

#define AS(r, c) As_[(r) * 36 + (c)]
#define BS(k, n) Bs_[(k) * 72 + (n)]

// ---- phase A, blocks 0..127: one 128x64 GEMM tile (3xTF32 MMA) ----
__device__ void gemm_tile(float* As_, float* Bs_, const float* __restrict__ x,
                          const float* __restrict__ W, int bx, int hh, int tid) {
    int lane = tid & 31, wid = tid >> 5;
    int bm = bx * 128;
    int m0 = (wid & 3) * 32;
    int n0 = (wid >> 2) * 32;
    float c[2][4][4] = {};

    for (int k0 = 0; k0 < D_EMB; k0 += 32) {
        #pragma unroll
        for (int l = 0; l < 4; l++) {                  // A: 128x32
            int idx = tid + l * 256;
            int r = idx >> 3, c4 = (idx & 7) * 4;
            float4 v = *(const float4*)&x[(bm + r) * D_EMB + k0 + c4];
            AS(r, c4) = v.x; AS(r, c4 + 1) = v.y; AS(r, c4 + 2) = v.z; AS(r, c4 + 3) = v.w;
        }
        #pragma unroll
        for (int l = 0; l < 2; l++) {                  // B: 32x64
            int idx = tid + l * 256;
            int kk = idx >> 4, c4 = (idx & 15) * 4;
            float4 v = *(const float4*)&W[hh * (D_EMB * DH) + (k0 + kk) * DH + c4];
            BS(kk, c4) = v.x; BS(kk, c4 + 1) = v.y; BS(kk, c4 + 2) = v.z; BS(kk, c4 + 3) = v.w;
        }
        __syncthreads();
        #pragma unroll
        for (int kc = 0; kc < 32; kc += 8) {
            unsigned ahi[2][4], alo[2][4];
            #pragma unroll
            for (int ms = 0; ms < 2; ms++) {
                int rb = m0 + ms * 16 + (lane >> 2);
                int kb = kc + (lane & 3);
                totf(AS(rb, kb),         ahi[ms][0], alo[ms][0]);
                totf(AS(rb + 8, kb),     ahi[ms][1], alo[ms][1]);
                totf(AS(rb, kb + 4),     ahi[ms][2], alo[ms][2]);
                totf(AS(rb + 8, kb + 4), ahi[ms][3], alo[ms][3]);
            }
            unsigned bhi[4][2], blo[4][2];
            #pragma unroll
            for (int ns = 0; ns < 4; ns++) {
                int nn = n0 + ns * 8 + (lane >> 2);
                int kb = kc + (lane & 3);
                totf(BS(kb, nn),     bhi[ns][0], blo[ns][0]);
                totf(BS(kb + 4, nn), bhi[ns][1], blo[ns][1]);
            }
            #pragma unroll
            for (int ms = 0; ms < 2; ms++)
                #pragma unroll
                for (int ns = 0; ns < 4; ns++) {
                    mma8(c[ms][ns], ahi[ms], bhi[ns]);
                    mma8(c[ms][ns], ahi[ms], blo[ns]);
                    mma8(c[ms][ns], alo[ms], bhi[ns]);
                }
        }
        __syncthreads();
    }
    #pragma unroll
    for (int ms = 0; ms < 2; ms++) {
        int row = bm + m0 + ms * 16 + (lane >> 2);
        #pragma unroll
        for (int ns = 0; ns < 4; ns++) {
            int col = hh * DH + n0 + ns * 8 + 2 * (lane & 3);
            *(float2*)&g_h[row * D_EMB + col]       = make_float2(c[ms][ns][0], c[ms][ns][1]);
            *(float2*)&g_h[(row + 8) * D_EMB + col] = make_float2(c[ms][ns][2], c[ms][ns][3]);
        }
    }
}

// ---- phase A, blocks 128..147: build + vec(smem) + edot ----
__device__ void helper_work(float* sm, const float* __restrict__ x,
                            const float* __restrict__ W,
                            const float* __restrict__ a_src,
                            const float* __restrict__ a_dst,
                            const int* __restrict__ ei,
                            const float* __restrict__ ev, int hb, int tid) {
    // build: dedup mark, return-free atomicOr (REDG). mask: edge_vals>0
    // (edge-MLP sigmoid strictly positive -> the 34-GFLOP MLP is dead code).
    for (int e = hb * 256 + tid; e < E_EDGES; e += 20 * 256) {
        if (ev[e] > 0.f) {
            int r = ei[e], c = ei[E_EDGES + e];
            atomicOr(&g_bits[r * BITW + (c >> 5)], 1u << (c & 31));
        }
    }
    // vec: gw_src/gw_dst (W[h]@a) into THIS block's smem (redundant per block,
    // avoids any cross-block handoff). sm[0..1023]=src, sm[1024..2047]=dst.
    #pragma unroll
    for (int l = 0; l < 4; l++) {
        int job = tid + l * 256;               // job = h*256 + d
        int h = job >> 8, d = job & 255;
        const float* wr = W + (h * D_EMB + d) * DH;
        float s = 0.f, t = 0.f;
        #pragma unroll
        for (int k = 0; k < DH; k++) {
            float w = wr[k];
            s += w * a_src[h * DH + k];
            t += w * a_dst[h * DH + k];
        }
        sm[job] = s;
        sm[1024 + job] = t;
    }
    __syncthreads();
    // edot: esrc[h][i] = x[i] . gw_src[h]; warp per row, strided over 160 warps
    int wid = tid >> 5, lane = tid & 31;
    for (int i = hb * 8 + wid; i < N_NODES; i += 20 * 8) {
        const float2* xr = (const float2*)x + i * 128;
        float2 v[4];
        #pragma unroll
        for (int p = 0; p < 4; p++) v[p] = xr[lane + 32 * p];
        #pragma unroll
        for (int h = 0; h < H_HEADS; h++) {
            float s = 0.f, d = 0.f;
            #pragma unroll
            for (int p = 0; p < 4; p++) {
                float2 a = *(const float2*)&sm[h * 256 + 2 * (lane + 32 * p)];
                float2 b = *(const float2*)&sm[1024 + h * 256 + 2 * (lane + 32 * p)];
                s += v[p].x * a.x + v[p].y * a.y;
                d += v[p].x * b.x + v[p].y * b.y;
            }
            #pragma unroll
            for (int o = 16; o; o >>= 1) {
                s += __shfl_xor_sync(0xffffffffu, s, o);
                d += __shfl_xor_sync(0xffffffffu, d, o);
            }
            if (lane == 0) { g_esrc[h * N_NODES + i] = s; g_edst[h * N_NODES + i] = d; }
        }
    }
}

// ---- phase B: scan bitmask -> neighbor list (+re-zero), then softmax ----
__device__ void scansoft_row(int r, int lane) {
    unsigned w[4];
    int cnt = 0;
    #pragma unroll
    for (int p = 0; p < 4; p++) {
        w[p] = g_bits[r * BITW + lane + 32 * p];
        cnt += __popc(w[p]);
    }
    #pragma unroll
    for (int p = 0; p < 4; p++)
        g_bits[r * BITW + lane + 32 * p] = 0u;       // restore zeros
    int base = cnt;
    #pragma unroll
    for (int o = 1; o < 32; o <<= 1) {
        int t = __shfl_up_sync(0xffffffffu, base, o);
        if (lane >= o) base += t;
    }
    int total = __shfl_sync(0xffffffffu, base, 31);
    base -= cnt;
    int pos = base;
    #pragma unroll
    for (int p = 0; p < 4; p++) {
        unsigned ww = w[p];
        int cbase = (lane + 32 * p) << 5;
        while (ww) {
            int b = __ffs(ww) - 1;
            ww &= ww - 1;
            if (pos < MAXDEG) g_nbr[r * MAXDEG + pos] = cbase + b;
            pos++;
        }
    }
    int deg = min(total, MAXDEG);
    if (lane == 31) g_deg[r] = deg;
    __syncwarp();
    if (deg == 0) return;

    const int* nb = &g_nbr[r * MAXDEG];
    if (deg <= 64) {                                 // ~99.99% of rows
        int c0 = nb[lane < deg ? lane : 0];
        int c1 = nb[(32 + lane) < deg ? 32 + lane : 0];
        #pragma unroll
        for (int h = 0; h < H_HEADS; h++) {
            float es = g_esrc[h * N_NODES + r];
            const float* ed = &g_edst[h * N_NODES];
            float* wt = &g_wt[(r * H_HEADS + h) * MAXDEG];
            float e0 = (lane < deg)      ? leaky(es + ed[c0]) : -3.0e38f;
            float e1 = (32 + lane < deg) ? leaky(es + ed[c1]) : -3.0e38f;
            float m = fmaxf(e0, e1);
            #pragma unroll
            for (int o = 16; o; o >>= 1) m = fmaxf(m, __shfl_xor_sync(0xffffffffu, m, o));
            float x0 = (lane < deg)      ? __expf(e0 - m) : 0.f;
            float x1 = (32 + lane < deg) ? __expf(e1 - m) : 0.f;
            float s = x0 + x1;
            #pragma unroll
            for (int o = 16; o; o >>= 1) s += __shfl_xor_sync(0xffffffffu, s, o);
            float inv = 1.0f / s;
            if (lane < deg)      wt[lane]      = x0 * inv;
            if (32 + lane < deg) wt[32 + lane] = x1 * inv;
        }
    } else {
        #pragma unroll
        for (int h = 0; h < H_HEADS; h++) {
            float es = g_esrc[h * N_NODES + r];
            const float* ed = &g_edst[h * N_NODES];
            float* wt = &g_wt[(r * H_HEADS + h) * MAXDEG];
            float m = -3.0e38f;
            for (int j = lane; j < deg; j += 32) m = fmaxf(m, leaky(es + ed[nb[j]]));
            #pragma unroll
            for (int o = 16; o; o >>= 1) m = fmaxf(m, __shfl_xor_sync(0xffffffffu, m, o));
            float s = 0.f;
            for (int j = lane; j < deg; j += 32) s += __expf(leaky(es + ed[nb[j]]) - m);
            #pragma unroll
            for (int o = 16; o; o >>= 1) s += __shfl_xor_sync(0xffffffffu, s, o);
            float inv = 1.0f / s;
            for (int j = lane; j < deg; j += 32)
                wt[j] = __expf(leaky(es + ed[nb[j]]) - m) * inv;
        }
    }
}

// ---- phase C: gather, warp per row (all 4 heads), 2x unroll ----
__device__ void gat_row(float* __restrict__ out, int i, int lane) {
    int deg = min(g_deg[i], MAXDEG);
    const int* nb = &g_nbr[i * MAXDEG];
    int ha = lane >> 4;
    const float* wta = &g_wt[(i * H_HEADS + ha)     * MAXDEG];
    const float* wtb = &g_wt[(i * H_HEADS + 2 + ha) * MAXDEG];
    const float4* h4 = (const float4*)g_h;
    int ca = lane, cb = 32 + lane;
    float4 A = make_float4(0.f, 0.f, 0.f, 0.f);
    float4 B = make_float4(0.f, 0.f, 0.f, 0.f);

    int j = 0;
    for (; j + 2 <= deg; j += 2) {
        int   c0 = nb[j],   c1 = nb[j + 1];
        float wa0 = wta[j], wa1 = wta[j + 1];
        float wb0 = wtb[j], wb1 = wtb[j + 1];
        float4 va0 = h4[c0 * 64 + ca], vb0 = h4[c0 * 64 + cb];
        float4 va1 = h4[c1 * 64 + ca], vb1 = h4[c1 * 64 + cb];
        A.x += wa0 * va0.x + wa1 * va1.x;  A.y += wa0 * va0.y + wa1 * va1.y;
        A.z += wa0 * va0.z + wa1 * va1.z;  A.w += wa0 * va0.w + wa1 * va1.w;
        B.x += wb0 * vb0.x + wb1 * vb1.x;  B.y += wb0 * vb0.y + wb1 * vb1.y;
        B.z += wb0 * vb0.z + wb1 * vb1.z;  B.w += wb0 * vb0.w + wb1 * vb1.w;
    }
    if (j < deg) {
        int c0 = nb[j];
        float wa = wta[j], wb = wtb[j];
        float4 va = h4[c0 * 64 + ca], vb = h4[c0 * 64 + cb];
        A.x += wa * va.x; A.y += wa * va.y; A.z += wa * va.z; A.w += wa * va.w;
        B.x += wb * vb.x; B.y += wb * vb.y; B.z += wb * vb.z; B.w += wb * vb.w;
    }
    if (deg == 0) {   // reference degenerates to uniform 1/N mean; P ~ e^-32
        float4 sa = make_float4(0.f, 0.f, 0.f, 0.f);
        float4 sb = make_float4(0.f, 0.f, 0.f, 0.f);
        for (int r = 0; r < N_NODES; r++) {
            float4 va = h4[r * 64 + ca], vb = h4[r * 64 + cb];
            sa.x += va.x; sa.y += va.y; sa.z += va.z; sa.w += va.w;
            sb.x += vb.x; sb.y += vb.y; sb.z += vb.z; sb.w += vb.w;
        }
        const float inv = 1.0f / N_NODES;
        A = make_float4(sa.x * inv, sa.y * inv, sa.z * inv, sa.w * inv);
        B = make_float4(sb.x * inv, sb.y * inv, sb.z * inv, sb.w * inv);
    }
    float4* o4 = (float4*)out;
    o4[i * 64 + ca] = A;
    o4[i * 64 + cb] = B;
}

// ---- the single persistent kernel ----
__global__ __launch_bounds__(256)
void k_mega(const float* __restrict__ x, const float* __restrict__ ev,
            const float* __restrict__ W, const float* __restrict__ a_src,
            const float* __restrict__ a_dst, const int* __restrict__ ei,
            float* __restrict__ out) {
    __shared__ float sm[128 * 36 + 32 * 72];   // 27.6KB: gemm tiles / gw vecs
    int bid = blockIdx.x, tid = threadIdx.x;

    // ---- phase A: blocks 0..127 gemm; blocks 128..147 build+vec+edot ----
    if (bid < 128) {
        gemm_tile(sm, sm + 128 * 36, x, W, bid & 31, bid >> 5, tid);
    } else {
        helper_work(sm, x, W, a_src, a_dst, ei, ev, bid - 128, tid);
    }
    gridsync(0);

    // ---- phase B: scan + softmax, warp per row ----
    {
        int gw = bid * 8 + (tid >> 5), lane = tid & 31;
        for (int r = gw; r < N_NODES; r += NWARPS) scansoft_row(r, lane);
    }
    gridsync(1);

    // ---- phase C: gather, warp per row ----
    {
        int gw = bid * 8 + (tid >> 5), lane = tid & 31;
        for (int i = gw; i < N_NODES; i += NWARPS) gat_row(out, i, lane);
    }
}

// ---------------------------------------------------------------------------
// inputs: 0 x 1 edge_vals 2 W1 3 b1 4 W2 5 b2 (2..5 dead code: mask depends
// only on sign of edge_vals) 6 W 7 a_src 8 a_dst 9 edge_index.
// ONE launch: the ~18us of multi-node graph overhead goes away.
// ---------------------------------------------------------------------------
extern "C" void kernel_launch(void* const* d_in, const int* in_sizes, int n_in,
                              void* d_out, int out_size) {
    const float* x     = (const float*)d_in[0];
    const float* ev    = (const float*)d_in[1];
    const float* W     = (const float*)d_in[6];
    const float* a_src = (const float*)d_in[7];
    const float* a_dst = (const float*)d_in[8];
    const int*   ei    = (const int*)d_in[9];
    float* out = (float*)d_out;

    k_mega<<<NBLK, 256>>>(x, ev, W, a_src, a_dst, ei, out);
}

// round 15
// speedup vs baseline: 1.3132x; 1.3132x over previous
#include <cuda_runtime.h>

#define N_NODES 4096
#define D_EMB   256
#define H_HEADS 4
#define DH      64
#define E_EDGES 131072
#define MAXDEG  256
#define ALPHA   0.2f
#define BITW    (N_NODES / 32)

// ---- scratch (__device__ globals; no allocations allowed) ----
// g_bits zero-initialized at load; k_tail re-zeros after reading, so every
// launch / graph replay sees a clean bitmask.
__device__ unsigned g_bits[N_NODES * BITW];
__device__ int      g_deg [N_NODES];
__device__ int      g_nbr [N_NODES * MAXDEG];
__device__ float    g_h   [N_NODES * D_EMB];
__device__ float    g_esrc[H_HEADS * N_NODES];
__device__ float    g_edst[H_HEADS * N_NODES];

__device__ __forceinline__ float leaky(float v) { return v >= 0.f ? v : ALPHA * v; }

// ---- 3xTF32 helpers: a = hi + lo; hi*hi + hi*lo + lo*hi ~ fp32 accuracy ----
__device__ __forceinline__ void totf(float a, unsigned& hi, unsigned& lo) {
    asm("cvt.rna.tf32.f32 %0, %1;" : "=r"(hi) : "f"(a));
    float r = a - __uint_as_float(hi);
    asm("cvt.rna.tf32.f32 %0, %1;" : "=r"(lo) : "f"(r));
}
__device__ __forceinline__ void mma8(float* c, const unsigned* a, const unsigned* b) {
    asm("mma.sync.aligned.m16n8k8.row.col.f32.tf32.tf32.f32 "
        "{%0,%1,%2,%3}, {%4,%5,%6,%7}, {%8,%9}, {%0,%1,%2,%3};"
        : "+f"(c[0]), "+f"(c[1]), "+f"(c[2]), "+f"(c[3])
        : "r"(a[0]), "r"(a[1]), "r"(a[2]), "r"(a[3]), "r"(b[0]), "r"(b[1]));
}

#define AS(r, c) As_[(r) * 36 + (c)]
#define BS(k, n) Bs_[(k) * 72 + (n)]

// ---- k_front, blocks 0..127: one 128x64 GEMM tile (3xTF32 MMA) ----
__device__ void gemm_tile(float* As_, float* Bs_, const float* __restrict__ x,
                          const float* __restrict__ W, int bx, int hh, int tid) {
    int lane = tid & 31, wid = tid >> 5;
    int bm = bx * 128;
    int m0 = (wid & 3) * 32;
    int n0 = (wid >> 2) * 32;
    float c[2][4][4] = {};

    for (int k0 = 0; k0 < D_EMB; k0 += 32) {
        #pragma unroll
        for (int l = 0; l < 4; l++) {                  // A: 128x32
            int idx = tid + l * 256;
            int r = idx >> 3, c4 = (idx & 7) * 4;
            float4 v = *(const float4*)&x[(bm + r) * D_EMB + k0 + c4];
            AS(r, c4) = v.x; AS(r, c4 + 1) = v.y; AS(r, c4 + 2) = v.z; AS(r, c4 + 3) = v.w;
        }
        #pragma unroll
        for (int l = 0; l < 2; l++) {                  // B: 32x64
            int idx = tid + l * 256;
            int kk = idx >> 4, c4 = (idx & 15) * 4;
            float4 v = *(const float4*)&W[hh * (D_EMB * DH) + (k0 + kk) * DH + c4];
            BS(kk, c4) = v.x; BS(kk, c4 + 1) = v.y; BS(kk, c4 + 2) = v.z; BS(kk, c4 + 3) = v.w;
        }
        __syncthreads();
        #pragma unroll
        for (int kc = 0; kc < 32; kc += 8) {
            unsigned ahi[2][4], alo[2][4];
            #pragma unroll
            for (int ms = 0; ms < 2; ms++) {
                int rb = m0 + ms * 16 + (lane >> 2);
                int kb = kc + (lane & 3);
                totf(AS(rb, kb),         ahi[ms][0], alo[ms][0]);
                totf(AS(rb + 8, kb),     ahi[ms][1], alo[ms][1]);
                totf(AS(rb, kb + 4),     ahi[ms][2], alo[ms][2]);
                totf(AS(rb + 8, kb + 4), ahi[ms][3], alo[ms][3]);
            }
            unsigned bhi[4][2], blo[4][2];
            #pragma unroll
            for (int ns = 0; ns < 4; ns++) {
                int nn = n0 + ns * 8 + (lane >> 2);
                int kb = kc + (lane & 3);
                totf(BS(kb, nn),     bhi[ns][0], blo[ns][0]);
                totf(BS(kb + 4, nn), bhi[ns][1], blo[ns][1]);
            }
            #pragma unroll
            for (int ms = 0; ms < 2; ms++)
                #pragma unroll
                for (int ns = 0; ns < 4; ns++) {
                    mma8(c[ms][ns], ahi[ms], bhi[ns]);
                    mma8(c[ms][ns], ahi[ms], blo[ns]);
                    mma8(c[ms][ns], alo[ms], bhi[ns]);
                }
        }
        __syncthreads();
    }
    #pragma unroll
    for (int ms = 0; ms < 2; ms++) {
        int row = bm + m0 + ms * 16 + (lane >> 2);
        #pragma unroll
        for (int ns = 0; ns < 4; ns++) {
            int col = hh * DH + n0 + ns * 8 + 2 * (lane & 3);
            *(float2*)&g_h[row * D_EMB + col]       = make_float2(c[ms][ns][0], c[ms][ns][1]);
            *(float2*)&g_h[(row + 8) * D_EMB + col] = make_float2(c[ms][ns][2], c[ms][ns][3]);
        }
    }
}

// ---- k_front, blocks 128..147: build + vec(smem) + edot ----
__device__ void helper_work(float* sm, const float* __restrict__ x,
                            const float* __restrict__ W,
                            const float* __restrict__ a_src,
                            const float* __restrict__ a_dst,
                            const int* __restrict__ ei,
                            const float* __restrict__ ev, int hb, int tid) {
    // build: dedup mark, return-free atomicOr (REDG). mask: edge_vals>0
    // (edge-MLP sigmoid strictly positive -> the 34-GFLOP MLP is dead code).
    for (int e = hb * 256 + tid; e < E_EDGES; e += 20 * 256) {
        if (ev[e] > 0.f) {
            int r = ei[e], c = ei[E_EDGES + e];
            atomicOr(&g_bits[r * BITW + (c >> 5)], 1u << (c & 31));
        }
    }
    // vec: gw_src/gw_dst (W[h]@a) into THIS block's smem (redundant per
    // block, no cross-block handoff). sm[0..1023]=src, sm[1024..2047]=dst.
    #pragma unroll
    for (int l = 0; l < 4; l++) {
        int job = tid + l * 256;               // job = h*256 + d
        int h = job >> 8, d = job & 255;
        const float* wr = W + (h * D_EMB + d) * DH;
        float s = 0.f, t = 0.f;
        #pragma unroll
        for (int k = 0; k < DH; k++) {
            float w = wr[k];
            s += w * a_src[h * DH + k];
            t += w * a_dst[h * DH + k];
        }
        sm[job] = s;
        sm[1024 + job] = t;
    }
    __syncthreads();
    // edot: esrc[h][i] = x[i] . gw_src[h]; warp per row over 160 warps
    int wid = tid >> 5, lane = tid & 31;
    for (int i = hb * 8 + wid; i < N_NODES; i += 20 * 8) {
        const float2* xr = (const float2*)x + i * 128;
        float2 v[4];
        #pragma unroll
        for (int p = 0; p < 4; p++) v[p] = xr[lane + 32 * p];
        #pragma unroll
        for (int h = 0; h < H_HEADS; h++) {
            float s = 0.f, d = 0.f;
            #pragma unroll
            for (int p = 0; p < 4; p++) {
                float2 a = *(const float2*)&sm[h * 256 + 2 * (lane + 32 * p)];
                float2 b = *(const float2*)&sm[1024 + h * 256 + 2 * (lane + 32 * p)];
                s += v[p].x * a.x + v[p].y * a.y;
                d += v[p].x * b.x + v[p].y * b.y;
            }
            #pragma unroll
            for (int o = 16; o; o >>= 1) {
                s += __shfl_xor_sync(0xffffffffu, s, o);
                d += __shfl_xor_sync(0xffffffffu, d, o);
            }
            if (lane == 0) { g_esrc[h * N_NODES + i] = s; g_edst[h * N_NODES + i] = d; }
        }
    }
}

// ---- kernel 1: block-specialized front (one launch = gemm+build+vec+edot) ----
__global__ __launch_bounds__(256)
void k_front(const float* __restrict__ x, const float* __restrict__ ev,
             const float* __restrict__ W, const float* __restrict__ a_src,
             const float* __restrict__ a_dst, const int* __restrict__ ei) {
    __shared__ float sm[128 * 36 + 32 * 72];   // 27.6KB
    int bid = blockIdx.x, tid = threadIdx.x;
    if (bid < 128) {
        gemm_tile(sm, sm + 128 * 36, x, W, bid & 31, bid >> 5, tid);
    } else {
        helper_work(sm, x, W, a_src, a_dst, ei, ev, bid - 128, tid);
    }
}

// ---- kernel 2: per-warp fused scansoft + gather. Weights live in SMEM ----
// (no g_wt global round trip). Warp owns row r end-to-end; __syncwarp
// orders its smem weight stores before its own gather loads.
__global__ __launch_bounds__(256)
void k_tail(float* __restrict__ out) {
    __shared__ float swt[8][H_HEADS][MAXDEG];          // 32 KB
    int wi = threadIdx.x >> 5, lane = threadIdx.x & 31;
    int r = blockIdx.x * 8 + wi;

    // ---- scan: bitmask -> neighbor list, re-zero bits ----
    unsigned w[4];
    int cnt = 0;
    #pragma unroll
    for (int p = 0; p < 4; p++) {
        w[p] = g_bits[r * BITW + lane + 32 * p];
        cnt += __popc(w[p]);
    }
    #pragma unroll
    for (int p = 0; p < 4; p++)
        g_bits[r * BITW + lane + 32 * p] = 0u;         // restore zeros
    int base = cnt;
    #pragma unroll
    for (int o = 1; o < 32; o <<= 1) {
        int t = __shfl_up_sync(0xffffffffu, base, o);
        if (lane >= o) base += t;
    }
    int total = __shfl_sync(0xffffffffu, base, 31);
    base -= cnt;
    int pos = base;
    #pragma unroll
    for (int p = 0; p < 4; p++) {
        unsigned ww = w[p];
        int cbase = (lane + 32 * p) << 5;
        while (ww) {
            int b = __ffs(ww) - 1;
            ww &= ww - 1;
            if (pos < MAXDEG) g_nbr[r * MAXDEG + pos] = cbase + b;
            pos++;
        }
    }
    int deg = min(total, MAXDEG);
    if (lane == 31) g_deg[r] = deg;
    __syncwarp();

    const int* nb = &g_nbr[r * MAXDEG];

    // ---- softmax weights into smem ----
    if (deg > 0) {
        if (deg <= 64) {                               // ~99.99% of rows
            int c0 = nb[lane < deg ? lane : 0];
            int c1 = nb[(32 + lane) < deg ? 32 + lane : 0];
            #pragma unroll
            for (int h = 0; h < H_HEADS; h++) {
                float es = g_esrc[h * N_NODES + r];
                const float* ed = &g_edst[h * N_NODES];
                float e0 = (lane < deg)      ? leaky(es + ed[c0]) : -3.0e38f;
                float e1 = (32 + lane < deg) ? leaky(es + ed[c1]) : -3.0e38f;
                float m = fmaxf(e0, e1);
                #pragma unroll
                for (int o = 16; o; o >>= 1) m = fmaxf(m, __shfl_xor_sync(0xffffffffu, m, o));
                float x0 = (lane < deg)      ? __expf(e0 - m) : 0.f;
                float x1 = (32 + lane < deg) ? __expf(e1 - m) : 0.f;
                float s = x0 + x1;
                #pragma unroll
                for (int o = 16; o; o >>= 1) s += __shfl_xor_sync(0xffffffffu, s, o);
                float inv = 1.0f / s;
                swt[wi][h][lane]      = x0 * inv;
                swt[wi][h][32 + lane] = x1 * inv;
            }
        } else {
            #pragma unroll
            for (int h = 0; h < H_HEADS; h++) {
                float es = g_esrc[h * N_NODES + r];
                const float* ed = &g_edst[h * N_NODES];
                float m = -3.0e38f;
                for (int j = lane; j < deg; j += 32) m = fmaxf(m, leaky(es + ed[nb[j]]));
                #pragma unroll
                for (int o = 16; o; o >>= 1) m = fmaxf(m, __shfl_xor_sync(0xffffffffu, m, o));
                float s = 0.f;
                for (int j = lane; j < deg; j += 32) s += __expf(leaky(es + ed[nb[j]]) - m);
                #pragma unroll
                for (int o = 16; o; o >>= 1) s += __shfl_xor_sync(0xffffffffu, s, o);
                float inv = 1.0f / s;
                for (int j = lane; j < deg; j += 32)
                    swt[wi][h][j] = __expf(leaky(es + ed[nb[j]]) - m) * inv;
            }
        }
    }
    __syncwarp();                                      // smem weights visible

    // ---- gather: lane owns two float4 column slots across the 4 heads ----
    int ha = lane >> 4;
    const float* wta = &swt[wi][ha][0];
    const float* wtb = &swt[wi][2 + ha][0];
    const float4* h4 = (const float4*)g_h;
    int ca = lane, cb = 32 + lane;
    float4 A = make_float4(0.f, 0.f, 0.f, 0.f);
    float4 B = make_float4(0.f, 0.f, 0.f, 0.f);

    int j = 0;
    for (; j + 2 <= deg; j += 2) {
        int   c0 = nb[j],   c1 = nb[j + 1];
        float wa0 = wta[j], wa1 = wta[j + 1];
        float wb0 = wtb[j], wb1 = wtb[j + 1];
        float4 va0 = h4[c0 * 64 + ca], vb0 = h4[c0 * 64 + cb];
        float4 va1 = h4[c1 * 64 + ca], vb1 = h4[c1 * 64 + cb];
        A.x += wa0 * va0.x + wa1 * va1.x;  A.y += wa0 * va0.y + wa1 * va1.y;
        A.z += wa0 * va0.z + wa1 * va1.z;  A.w += wa0 * va0.w + wa1 * va1.w;
        B.x += wb0 * vb0.x + wb1 * vb1.x;  B.y += wb0 * vb0.y + wb1 * vb1.y;
        B.z += wb0 * vb0.z + wb1 * vb1.z;  B.w += wb0 * vb0.w + wb1 * vb1.w;
    }
    if (j < deg) {
        int c0 = nb[j];
        float wa = wta[j], wb = wtb[j];
        float4 va = h4[c0 * 64 + ca], vb = h4[c0 * 64 + cb];
        A.x += wa * va.x; A.y += wa * va.y; A.z += wa * va.z; A.w += wa * va.w;
        B.x += wb * vb.x; B.y += wb * vb.y; B.z += wb * vb.z; B.w += wb * vb.w;
    }
    if (deg == 0) {   // reference degenerates to uniform 1/N mean; P ~ e^-32
        float4 sa = make_float4(0.f, 0.f, 0.f, 0.f);
        float4 sb = make_float4(0.f, 0.f, 0.f, 0.f);
        for (int rr = 0; rr < N_NODES; rr++) {
            float4 va = h4[rr * 64 + ca], vb = h4[rr * 64 + cb];
            sa.x += va.x; sa.y += va.y; sa.z += va.z; sa.w += va.w;
            sb.x += vb.x; sb.y += vb.y; sb.z += vb.z; sb.w += vb.w;
        }
        const float inv = 1.0f / N_NODES;
        A = make_float4(sa.x * inv, sa.y * inv, sa.z * inv, sa.w * inv);
        B = make_float4(sb.x * inv, sb.y * inv, sb.z * inv, sb.w * inv);
    }
    float4* o4 = (float4*)out;
    o4[r * 64 + ca] = A;
    o4[r * 64 + cb] = B;
}

// ---------------------------------------------------------------------------
// inputs: 0 x 1 edge_vals 2 W1 3 b1 4 W2 5 b2 (2..5 dead code: mask depends
// only on sign of edge_vals) 6 W 7 a_src 8 a_dst 9 edge_index.
// TWO launches, both full-parallelism:
//   k_front: 128 gemm blocks + 20 helper blocks (build/vec/edot), grid=148
//   k_tail : 512 blocks, warp-per-row fused scansoft+gather (smem weights)
// ---------------------------------------------------------------------------
extern "C" void kernel_launch(void* const* d_in, const int* in_sizes, int n_in,
                              void* d_out, int out_size) {
    const float* x     = (const float*)d_in[0];
    const float* ev    = (const float*)d_in[1];
    const float* W     = (const float*)d_in[6];
    const float* a_src = (const float*)d_in[7];
    const float* a_dst = (const float*)d_in[8];
    const int*   ei    = (const int*)d_in[9];
    float* out = (float*)d_out;

    k_front<<<148, 256>>>(x, ev, W, a_src, a_dst, ei);
    k_tail<<<N_NODES / 8, 256>>>(out);
}

// round 17
// speedup vs baseline: 2.6205x; 1.9956x over previous
#include <cuda_runtime.h>

#define N_NODES 4096
#define D_EMB   256
#define H_HEADS 4
#define DH      64
#define E_EDGES 131072
#define MAXDEG  256
#define ALPHA   0.2f
#define BITW    (N_NODES / 32)

// ---- scratch (__device__ globals; no allocations allowed) ----
// g_bits zero-initialized at load; k_tail re-zeros after reading, so every
// launch / graph replay sees a clean bitmask.
__device__ unsigned g_bits[N_NODES * BITW];
__device__ int      g_deg [N_NODES];
__device__ int      g_nbr [N_NODES * MAXDEG];
__device__ float    g_h   [N_NODES * D_EMB];
__device__ float    g_esrc[H_HEADS * N_NODES];
__device__ float    g_edst[H_HEADS * N_NODES];
__device__ float    g_wt  [N_NODES * H_HEADS * MAXDEG];  // deg>64 fallback only
__device__ float    gw_src[H_HEADS * D_EMB];
__device__ float    gw_dst[H_HEADS * D_EMB];

__device__ __forceinline__ float leaky(float v) { return v >= 0.f ? v : ALPHA * v; }
__device__ __forceinline__ unsigned f2u(float v) { return __float_as_uint(v); }

// ---- 3xTF32: a = hi + lo; hi*hi + hi*lo + lo*hi ~ fp32 accuracy ----
__device__ __forceinline__ float2 totf2(float a) {
    unsigned hi, lo;
    asm("cvt.rna.tf32.f32 %0, %1;" : "=r"(hi) : "f"(a));
    float r = a - __uint_as_float(hi);
    asm("cvt.rna.tf32.f32 %0, %1;" : "=r"(lo) : "f"(r));
    return make_float2(__uint_as_float(hi), __uint_as_float(lo));
}
__device__ __forceinline__ void mma8(float* c, const unsigned* a, const unsigned* b) {
    asm("mma.sync.aligned.m16n8k8.row.col.f32.tf32.tf32.f32 "
        "{%0,%1,%2,%3}, {%4,%5,%6,%7}, {%8,%9}, {%0,%1,%2,%3};"
        : "+f"(c[0]), "+f"(c[1]), "+f"(c[2]), "+f"(c[3])
        : "r"(a[0]), "r"(a[1]), "r"(a[2]), "r"(a[3]), "r"(b[0]), "r"(b[1]));
}

// ---------------------------------------------------------------------------
// 1. dedup mark, return-free atomicOr (REDG). mask: edge_vals>0 <=>
//    new_vals>0 (edge-MLP sigmoid strictly positive -> 34 GFLOP dead code).
//    R12-measured form: 1 edge/thread, grid 512. 4.9us.
// ---------------------------------------------------------------------------
__global__ void k_build(const int* __restrict__ ei, const float* __restrict__ ev) {
    int e = blockIdx.x * blockDim.x + threadIdx.x;
    if (e >= E_EDGES) return;
    if (!(ev[e] > 0.f)) return;
    int r = ei[e];
    int c = ei[E_EDGES + e];
    atomicOr(&g_bits[r * BITW + (c >> 5)], 1u << (c & 31));
}

// ---------------------------------------------------------------------------
// 2. gw_src[h] = W[h] @ a_src[h] (and dst). Warp per (h,d).
// ---------------------------------------------------------------------------
__global__ void k_vec(const float* __restrict__ W, const float* __restrict__ a_src,
                      const float* __restrict__ a_dst) {
    int wid = blockIdx.x * 8 + (threadIdx.x >> 5);
    int lane = threadIdx.x & 31;
    int h = wid >> 8, d = wid & 255;
    const float* wr = W + (h * D_EMB + d) * DH;
    float w0 = wr[lane], w1 = wr[32 + lane];
    float s = w0 * a_src[h * DH + lane] + w1 * a_src[h * DH + 32 + lane];
    float t = w0 * a_dst[h * DH + lane] + w1 * a_dst[h * DH + 32 + lane];
    #pragma unroll
    for (int o = 16; o; o >>= 1) {
        s += __shfl_xor_sync(0xffffffffu, s, o);
        t += __shfl_xor_sync(0xffffffffu, t, o);
    }
    if (lane == 0) { gw_src[h * D_EMB + d] = s; gw_dst[h * D_EMB + d] = t; }
}

// ---------------------------------------------------------------------------
// 3. esrc/edst GEMV: warp per row, 8 dots per warp.
// ---------------------------------------------------------------------------
__global__ void k_edot(const float* __restrict__ x) {
    __shared__ float2 ws[H_HEADS][128], wd[H_HEADS][128];
    int tid = threadIdx.x;
    for (int l = tid; l < 512; l += 256) {
        ((float2*)ws)[l] = ((const float2*)gw_src)[l];
        ((float2*)wd)[l] = ((const float2*)gw_dst)[l];
    }
    __syncthreads();
    int wi = tid >> 5, lane = tid & 31;
    int i = blockIdx.x * 8 + wi;
    const float2* xr = (const float2*)x + i * 128;
    float2 v[4];
    #pragma unroll
    for (int p = 0; p < 4; p++) v[p] = xr[lane + 32 * p];
    #pragma unroll
    for (int h = 0; h < H_HEADS; h++) {
        float s = 0.f, d = 0.f;
        #pragma unroll
        for (int p = 0; p < 4; p++) {
            float2 a = ws[h][lane + 32 * p];
            float2 b = wd[h][lane + 32 * p];
            s += v[p].x * a.x + v[p].y * a.y;
            d += v[p].x * b.x + v[p].y * b.y;
        }
        #pragma unroll
        for (int o = 16; o; o >>= 1) {
            s += __shfl_xor_sync(0xffffffffu, s, o);
            d += __shfl_xor_sync(0xffffffffu, d, o);
        }
        if (lane == 0) { g_esrc[h * N_NODES + i] = s; g_edst[h * N_NODES + i] = d; }
    }
}

// ---------------------------------------------------------------------------
// 4. h = x @ Wf via 3xTF32 MMA, conversions HOISTED to the smem fill:
//    smem holds (hi,lo) float2 pairs -> inner loop is pure LDS.64 + MMA.
//    64x64 tiles, grid (64,4) = 256 blocks (~2/SM, 16 warps/SM).
//    Warp tile 16x32: m0=(wid&3)*16, n0=(wid>>2)*32.
//    Conflict-free: A addr (4r+k), B addr (8k+n) distinct per half-warp.
// ---------------------------------------------------------------------------
__global__ __launch_bounds__(256) void k_gemm(const float* __restrict__ x,
                                              const float* __restrict__ W) {
    __shared__ float2 As[64][36];   // 18 KB  (hi,lo)
    __shared__ float2 Bs[32][72];   // 18 KB
    int tid = threadIdx.x, lane = tid & 31, wid = tid >> 5;
    int bm = blockIdx.x * 64;
    int hh = blockIdx.y;
    int m0 = (wid & 3) * 16;
    int n0 = (wid >> 2) * 32;

    float c[4][4] = {};             // [ns][frag]

    for (int k0 = 0; k0 < D_EMB; k0 += 32) {
        #pragma unroll
        for (int l = 0; l < 2; l++) {                  // A: 64x32
            int idx = tid + l * 256;
            int r = idx >> 3, c4 = (idx & 7) * 4;
            float4 v = *(const float4*)&x[(bm + r) * D_EMB + k0 + c4];
            As[r][c4]     = totf2(v.x);
            As[r][c4 + 1] = totf2(v.y);
            As[r][c4 + 2] = totf2(v.z);
            As[r][c4 + 3] = totf2(v.w);
        }
        #pragma unroll
        for (int l = 0; l < 2; l++) {                  // B: 32x64
            int idx = tid + l * 256;
            int kk = idx >> 4, c4 = (idx & 15) * 4;
            float4 v = *(const float4*)&W[hh * (D_EMB * DH) + (k0 + kk) * DH + c4];
            Bs[kk][c4]     = totf2(v.x);
            Bs[kk][c4 + 1] = totf2(v.y);
            Bs[kk][c4 + 2] = totf2(v.z);
            Bs[kk][c4 + 3] = totf2(v.w);
        }
        __syncthreads();
        #pragma unroll
        for (int kc = 0; kc < 32; kc += 8) {
            int rb = m0 + (lane >> 2);
            int kb = kc + (lane & 3);
            float2 a0 = As[rb][kb],     a1 = As[rb + 8][kb];
            float2 a2 = As[rb][kb + 4], a3 = As[rb + 8][kb + 4];
            unsigned ahi[4] = { f2u(a0.x), f2u(a1.x), f2u(a2.x), f2u(a3.x) };
            unsigned alo[4] = { f2u(a0.y), f2u(a1.y), f2u(a2.y), f2u(a3.y) };
            #pragma unroll
            for (int ns = 0; ns < 4; ns++) {
                int nn = n0 + ns * 8 + (lane >> 2);
                float2 b0 = Bs[kb][nn], b1 = Bs[kb + 4][nn];
                unsigned bhi[2] = { f2u(b0.x), f2u(b1.x) };
                unsigned blo[2] = { f2u(b0.y), f2u(b1.y) };
                mma8(c[ns], ahi, bhi);
                mma8(c[ns], ahi, blo);
                mma8(c[ns], alo, bhi);
            }
        }
        __syncthreads();
    }
    int row = bm + m0 + (lane >> 2);
    #pragma unroll
    for (int ns = 0; ns < 4; ns++) {
        int col = hh * DH + n0 + ns * 8 + 2 * (lane & 3);
        *(float2*)&g_h[row * D_EMB + col]       = make_float2(c[ns][0], c[ns][1]);
        *(float2*)&g_h[(row + 8) * D_EMB + col] = make_float2(c[ns][2], c[ns][3]);
    }
}

// ---------------------------------------------------------------------------
// 5. fused tail: warp per row. scan (bitmask -> list, re-zero) -> softmax
//    weights into 8KB smem (deg<=64; global fallback for rare deg>64) ->
//    gather with 4x unroll (8 LDG.128 in flight). High occupancy (smem 8KB).
// ---------------------------------------------------------------------------
__global__ __launch_bounds__(256) void k_tail(float* __restrict__ out) {
    __shared__ float swt[8][H_HEADS][64];              // 8 KB
    int wi = threadIdx.x >> 5, lane = threadIdx.x & 31;
    int r = blockIdx.x * 8 + wi;

    // ---- scan ----
    unsigned w[4];
    int cnt = 0;
    #pragma unroll
    for (int p = 0; p < 4; p++) {
        w[p] = g_bits[r * BITW + lane + 32 * p];
        cnt += __popc(w[p]);
    }
    #pragma unroll
    for (int p = 0; p < 4; p++)
        g_bits[r * BITW + lane + 32 * p] = 0u;         // restore zeros
    int base = cnt;
    #pragma unroll
    for (int o = 1; o < 32; o <<= 1) {
        int t = __shfl_up_sync(0xffffffffu, base, o);
        if (lane >= o) base += t;
    }
    int total = __shfl_sync(0xffffffffu, base, 31);
    base -= cnt;
    int pos = base;
    #pragma unroll
    for (int p = 0; p < 4; p++) {
        unsigned ww = w[p];
        int cbase = (lane + 32 * p) << 5;
        while (ww) {
            int b = __ffs(ww) - 1;
            ww &= ww - 1;
            if (pos < MAXDEG) g_nbr[r * MAXDEG + pos] = cbase + b;
            pos++;
        }
    }
    int deg = min(total, MAXDEG);
    if (lane == 31) g_deg[r] = deg;
    __syncwarp();

    const int* nb = &g_nbr[r * MAXDEG];
    bool small = (deg <= 64);

    // ---- softmax weights ----
    if (deg > 0) {
        if (small) {                                   // ~all rows
            int c0 = nb[lane < deg ? lane : 0];
            int c1 = nb[(32 + lane) < deg ? 32 + lane : 0];
            #pragma unroll
            for (int h = 0; h < H_HEADS; h++) {
                float es = g_esrc[h * N_NODES + r];
                const float* ed = &g_edst[h * N_NODES];
                float e0 = (lane < deg)      ? leaky(es + ed[c0]) : -3.0e38f;
                float e1 = (32 + lane < deg) ? leaky(es + ed[c1]) : -3.0e38f;
                float m = fmaxf(e0, e1);
                #pragma unroll
                for (int o = 16; o; o >>= 1) m = fmaxf(m, __shfl_xor_sync(0xffffffffu, m, o));
                float x0 = (lane < deg)      ? __expf(e0 - m) : 0.f;
                float x1 = (32 + lane < deg) ? __expf(e1 - m) : 0.f;
                float s = x0 + x1;
                #pragma unroll
                for (int o = 16; o; o >>= 1) s += __shfl_xor_sync(0xffffffffu, s, o);
                float inv = 1.0f / s;
                swt[wi][h][lane] = x0 * inv;
                if (32 + lane < 64) swt[wi][h][32 + lane] = x1 * inv;
            }
        } else {                                       // rare: global buffer
            #pragma unroll
            for (int h = 0; h < H_HEADS; h++) {
                float es = g_esrc[h * N_NODES + r];
                const float* ed = &g_edst[h * N_NODES];
                float* wt = &g_wt[(r * H_HEADS + h) * MAXDEG];
                float m = -3.0e38f;
                for (int j = lane; j < deg; j += 32) m = fmaxf(m, leaky(es + ed[nb[j]]));
                #pragma unroll
                for (int o = 16; o; o >>= 1) m = fmaxf(m, __shfl_xor_sync(0xffffffffu, m, o));
                float s = 0.f;
                for (int j = lane; j < deg; j += 32) s += __expf(leaky(es + ed[nb[j]]) - m);
                #pragma unroll
                for (int o = 16; o; o >>= 1) s += __shfl_xor_sync(0xffffffffu, s, o);
                float inv = 1.0f / s;
                for (int j = lane; j < deg; j += 32)
                    wt[j] = __expf(leaky(es + ed[nb[j]]) - m) * inv;
            }
        }
    }
    __syncwarp();

    // ---- gather: lane owns two float4 column slots across 4 heads ----
    int ha = lane >> 4;
    const float* wta = small ? &swt[wi][ha][0]     : &g_wt[(r * H_HEADS + ha)     * MAXDEG];
    const float* wtb = small ? &swt[wi][2 + ha][0] : &g_wt[(r * H_HEADS + 2 + ha) * MAXDEG];
    const float4* h4 = (const float4*)g_h;
    int ca = lane, cb = 32 + lane;
    float4 A = make_float4(0.f, 0.f, 0.f, 0.f);
    float4 B = make_float4(0.f, 0.f, 0.f, 0.f);

    int j = 0;
    for (; j + 4 <= deg; j += 4) {
        int c0 = nb[j], c1 = nb[j + 1], c2 = nb[j + 2], c3 = nb[j + 3];
        float wa0 = wta[j], wa1 = wta[j + 1], wa2 = wta[j + 2], wa3 = wta[j + 3];
        float wb0 = wtb[j], wb1 = wtb[j + 1], wb2 = wtb[j + 2], wb3 = wtb[j + 3];
        float4 va0 = h4[c0 * 64 + ca], vb0 = h4[c0 * 64 + cb];
        float4 va1 = h4[c1 * 64 + ca], vb1 = h4[c1 * 64 + cb];
        float4 va2 = h4[c2 * 64 + ca], vb2 = h4[c2 * 64 + cb];
        float4 va3 = h4[c3 * 64 + ca], vb3 = h4[c3 * 64 + cb];
        A.x += wa0 * va0.x + wa1 * va1.x + wa2 * va2.x + wa3 * va3.x;
        A.y += wa0 * va0.y + wa1 * va1.y + wa2 * va2.y + wa3 * va3.y;
        A.z += wa0 * va0.z + wa1 * va1.z + wa2 * va2.z + wa3 * va3.z;
        A.w += wa0 * va0.w + wa1 * va1.w + wa2 * va2.w + wa3 * va3.w;
        B.x += wb0 * vb0.x + wb1 * vb1.x + wb2 * vb2.x + wb3 * vb3.x;
        B.y += wb0 * vb0.y + wb1 * vb1.y + wb2 * vb2.y + wb3 * vb3.y;
        B.z += wb0 * vb0.z + wb1 * vb1.z + wb2 * vb2.z + wb3 * vb3.z;
        B.w += wb0 * vb0.w + wb1 * vb1.w + wb2 * vb2.w + wb3 * vb3.w;
    }
    for (; j < deg; j++) {
        int c0 = nb[j];
        float wa = wta[j], wb = wtb[j];
        float4 va = h4[c0 * 64 + ca], vb = h4[c0 * 64 + cb];
        A.x += wa * va.x; A.y += wa * va.y; A.z += wa * va.z; A.w += wa * va.w;
        B.x += wb * vb.x; B.y += wb * vb.y; B.z += wb * vb.z; B.w += wb * vb.w;
    }
    if (deg == 0) {   // reference degenerates to uniform 1/N mean; P ~ e^-32
        float4 sa = make_float4(0.f, 0.f, 0.f, 0.f);
        float4 sb = make_float4(0.f, 0.f, 0.f, 0.f);
        for (int rr = 0; rr < N_NODES; rr++) {
            float4 va = h4[rr * 64 + ca], vb = h4[rr * 64 + cb];
            sa.x += va.x; sa.y += va.y; sa.z += va.z; sa.w += va.w;
            sb.x += vb.x; sb.y += vb.y; sb.z += vb.z; sb.w += vb.w;
        }
        const float inv = 1.0f / N_NODES;
        A = make_float4(sa.x * inv, sa.y * inv, sa.z * inv, sa.w * inv);
        B = make_float4(sb.x * inv, sb.y * inv, sb.z * inv, sb.w * inv);
    }
    float4* o4 = (float4*)out;
    o4[r * 64 + ca] = A;
    o4[r * 64 + cb] = B;
}

// ---------------------------------------------------------------------------
// inputs: 0 x 1 edge_vals 2 W1 3 b1 4 W2 5 b2 (2..5 dead code: mask depends
// only on sign of edge_vals) 6 W 7 a_src 8 a_dst 9 edge_index.
// DAG (proven R12 shape): main: build -> [edot][gemm] -> tail
//                         s2: gemm    s3: vec -> edot
// ---------------------------------------------------------------------------
extern "C" void kernel_launch(void* const* d_in, const int* in_sizes, int n_in,
                              void* d_out, int out_size) {
    const float* x     = (const float*)d_in[0];
    const float* ev    = (const float*)d_in[1];
    const float* W     = (const float*)d_in[6];
    const float* a_src = (const float*)d_in[7];
    const float* a_dst = (const float*)d_in[8];
    const int*   ei    = (const int*)d_in[9];
    float* out = (float*)d_out;

    static cudaStream_t s2 = nullptr, s3 = nullptr;
    static cudaEvent_t  e_fork = nullptr, e_gemm = nullptr, e_edot = nullptr;
    if (!s2) {
        cudaStreamCreateWithFlags(&s2, cudaStreamNonBlocking);
        cudaStreamCreateWithFlags(&s3, cudaStreamNonBlocking);
        cudaEventCreateWithFlags(&e_fork, cudaEventDisableTiming);
        cudaEventCreateWithFlags(&e_gemm, cudaEventDisableTiming);
        cudaEventCreateWithFlags(&e_edot, cudaEventDisableTiming);
    }

    cudaEventRecord(e_fork, 0);
    cudaStreamWaitEvent(s2, e_fork, 0);
    cudaStreamWaitEvent(s3, e_fork, 0);

    k_gemm<<<dim3(N_NODES / 64, H_HEADS), 256, 0, s2>>>(x, W);
    cudaEventRecord(e_gemm, s2);

    k_vec<<<128, 256, 0, s3>>>(W, a_src, a_dst);
    k_edot<<<N_NODES / 8, 256, 0, s3>>>(x);
    cudaEventRecord(e_edot, s3);

    k_build<<<E_EDGES / 256, 256>>>(ei, ev);

    cudaStreamWaitEvent(0, e_edot, 0);
    cudaStreamWaitEvent(0, e_gemm, 0);
    k_tail<<<N_NODES / 8, 256>>>(out);
}